// round 14
// baseline (speedup 1.0000x reference)
#include <cuda_runtime.h>
#include <cuda_fp16.h>
#include <cstdint>

// ---------------------------------------------------------------------------
// Problem constants
// ---------------------------------------------------------------------------
static constexpr int BATCH = 8192;
static constexpr int D     = 2048;           // input feature dim (K of GEMM)
static constexpr int DK    = 1024;           // projection dim
static constexpr int ROWS  = BATCH * 3;      // 24576 rows per tensor
static constexpr int GM    = ROWS * 2;       // 49152 (img rows then text rows)
static constexpr int GN    = 2 * DK;         // 2048  (Q cols then K cols)
static constexpr int GK    = D;              // 2048
static constexpr float NORM_FACT = 0.03125f; // 1/sqrt(1024)

// GEMM tiling (proven config): 128x256 CTA tile, 8 warps (2x4), 64x64 warp
static constexpr int TILE_M = 128;
static constexpr int TILE_N = 256;
static constexpr int BK     = 64;            // k elems per chunk
static constexpr int NCHUNK = GK / BK;       // 32

// SMEM rings:
//   A32: fp32 staging, 272B-padded rows (2-way LDS conflicts max), ring 2
//   A16: converted fp16 tile (swizzled, 128B rows), ring 2
//   B  : fp16 tile from g_B (swizzled), ring 3
static constexpr int A32_TILE = TILE_M * 272;            // 34816
static constexpr int A16_TILE = TILE_M * 128;            // 16384
static constexpr int B_TILE   = TILE_N * 128;            // 32768
static constexpr int A32_OFF  = 0;
static constexpr int A16_OFF  = 2 * A32_TILE;            // 69632
static constexpr int B_OFF    = A16_OFF + 2 * A16_TILE;  // 102400
static constexpr int SMEM_TOTAL = B_OFF + 3 * B_TILE;    // 200704

static constexpr int NTILES_M = GM / TILE_M;  // 384
static constexpr int NTILES_N = GN / TILE_N;  // 8
static constexpr int NTILES   = NTILES_M * NTILES_N;  // 3072

// ---------------------------------------------------------------------------
// Device scratch
// ---------------------------------------------------------------------------
__device__ __align__(16) __half g_B[(size_t)GN * GK];
__device__ __align__(16) __half g_QK[(size_t)GM * GN];

// ---------------------------------------------------------------------------
// PTX helpers (portable sm_80-era ISA: cp.async, ldmatrix, mma.sync)
// ---------------------------------------------------------------------------
__device__ __forceinline__ uint32_t smem_u32(const void* p) {
    uint32_t a;
    asm("{ .reg .u64 t; cvta.to.shared.u64 t, %1; cvt.u32.u64 %0, t; }" : "=r"(a) : "l"(p));
    return a;
}
__device__ __forceinline__ void cp16(uint32_t dst, const void* src) {
    asm volatile("cp.async.cg.shared.global [%0], [%1], 16;" :: "r"(dst), "l"(src));
}
__device__ __forceinline__ void cp_commit() {
    asm volatile("cp.async.commit_group;" ::: "memory");
}
template <int N>
__device__ __forceinline__ void cp_wait() {
    asm volatile("cp.async.wait_group %0;" :: "n"(N) : "memory");
}
__device__ __forceinline__ void ldmx4(uint32_t* r, uint32_t addr) {
    asm volatile("ldmatrix.sync.aligned.m8n8.x4.shared.b16 {%0,%1,%2,%3}, [%4];"
                 : "=r"(r[0]), "=r"(r[1]), "=r"(r[2]), "=r"(r[3]) : "r"(addr));
}
__device__ __forceinline__ void mma_fp16(float* c, const uint32_t* a, uint32_t b0, uint32_t b1) {
    asm volatile(
        "mma.sync.aligned.m16n8k16.row.col.f32.f16.f16.f32 "
        "{%0,%1,%2,%3}, {%4,%5,%6,%7}, {%8,%9}, {%0,%1,%2,%3};"
        : "+f"(c[0]), "+f"(c[1]), "+f"(c[2]), "+f"(c[3])
        : "r"(a[0]), "r"(a[1]), "r"(a[2]), "r"(a[3]), "r"(b0), "r"(b1));
}
__device__ __forceinline__ uint32_t pack_h2(float x, float y) {
    const __half2 h = __floats2half2_rn(x, y);
    return *(const uint32_t*)&h;
}

// ---------------------------------------------------------------------------
// Convert kernel: B (weights) fp32 -> fp16 only. A is converted inside GEMM.
// ---------------------------------------------------------------------------
static constexpr size_t B_F8 = (size_t)GN * GK / 8;
static constexpr size_t B_HALF8 = (size_t)DK * GK / 8;

__global__ void convertB_kernel(const float* __restrict__ Wq,
                                const float* __restrict__ Wk)
{
    const size_t j = (size_t)blockIdx.x * blockDim.x + threadIdx.x;  // float8 index
    const float4* src = (j < B_HALF8) ? (const float4*)Wq : (const float4*)Wk;
    const size_t off = (j < B_HALF8) ? j : (j - B_HALF8);
    const float4 v0 = src[2 * off];
    const float4 v1 = src[2 * off + 1];
    uint4 o;
    o.x = pack_h2(v0.x, v0.y);
    o.y = pack_h2(v0.z, v0.w);
    o.z = pack_h2(v1.x, v1.y);
    o.w = pack_h2(v1.z, v1.w);
    ((uint4*)g_B)[j] = o;
}

// ---------------------------------------------------------------------------
// Persistent mma.sync fp16 GEMM with in-kernel A conversion:
//   A loaded fp32 from img/text via cp.async -> A32 ring;
//   each thread converts ITS OWN 128B region -> swizzled fp16 A16 ring
//   (same-thread visibility => single __syncthreads per chunk retained);
//   conversion targets chunk u+1 while chunk u computes (hidden in shadow).
// 128x256 CTA tile, 8 warps (2x4), 64x64 warp tile, chunk-continuous tiles.
// ---------------------------------------------------------------------------
__global__ void __launch_bounds__(256, 1) gemm_mma_kernel(
    const float* __restrict__ img, const float* __restrict__ text,
    const float* __restrict__ bq,  const float* __restrict__ bk)
{
    extern __shared__ char smem[];
    const uint32_t sbase = smem_u32(smem);
    const int tid  = threadIdx.x;
    const int warp = tid >> 5;
    const int lane = tid & 31;
    const int bid  = blockIdx.x;
    const int grid = gridDim.x;

    const int wm = warp & 1;     // M half (64 rows)
    const int wn = warp >> 1;    // N quarter (64 cols)

    const int ntiles  = (NTILES - bid + grid - 1) / grid;
    if (ntiles <= 0) return;
    const int total_u = ntiles * NCHUNK;

    // ---- load geometry (tile-independent part) ----
    const int lr  = tid >> 1;          // 0..127 (row within tile)
    const int lc0 = (tid & 1) * 4;     // first fp16 16B-unit (0 or 4)
    const int ah  = tid & 1;           // A half-row selector

    uint32_t swoff[4];                 // swizzled fp16 offsets (row lr, units lc0..lc0+3)
    #pragma unroll
    for (int i = 0; i < 4; i++)
        swoff[i] = (uint32_t)(lr * 128 + (((lc0 + i) ^ (lr & 7)) * 16));

    const uint32_t a32thr = (uint32_t)(lr * 272 + ah * 128);  // thread's A32 region

    // u -> (tile, chunk); tile -> (bm, bn) with bn fastest (A reuse in L2)
    auto load_stage = [&](int u) {
        const int t  = bid + (u >> 5) * grid;
        const int c  = u & 31;
        const int bm = (t >> 3) * TILE_M;
        const int bn = (t & 7) * TILE_N;
        // A: fp32 directly from img/text (tile never straddles: 24576%128==0)
        const float* aP = ((bm < ROWS) ? (img + (size_t)(bm + lr) * D)
                                       : (text + (size_t)(bm + lr - ROWS) * D))
                          + c * BK + ah * 32;
        const uint32_t a32 = sbase + A32_OFF + (u & 1) * A32_TILE + a32thr;
        #pragma unroll
        for (int i = 0; i < 8; i++)
            cp16(a32 + i * 16, aP + i * 4);
        // B: fp16 from g_B
        const __half* gB0 = g_B + (size_t)(bn + lr) * GK + lc0 * 8 + (size_t)c * BK;
        const __half* gB1 = gB0 + (size_t)128 * GK;
        const uint32_t bs = sbase + B_OFF + (u % 3) * B_TILE;
        #pragma unroll
        for (int i = 0; i < 4; i++) {
            cp16(bs +         swoff[i], gB0 + i * 8);
            cp16(bs + 16384 + swoff[i], gB1 + i * 8);
        }
        cp_commit();
    };

    // convert chunk cv: thread's own A32 region -> swizzled fp16 A16
    auto convert = [&](int cv) {
        const char* p32 = smem + A32_OFF + (cv & 1) * A32_TILE + a32thr;
        char* p16 = smem + A16_OFF + (cv & 1) * A16_TILE;
        #pragma unroll
        for (int i = 0; i < 4; i++) {
            const float4 f0 = *(const float4*)(p32 + i * 32);
            const float4 f1 = *(const float4*)(p32 + i * 32 + 16);
            uint4 o;
            o.x = pack_h2(f0.x, f0.y);
            o.y = pack_h2(f0.z, f0.w);
            o.z = pack_h2(f1.x, f1.y);
            o.w = pack_h2(f1.z, f1.w);
            *(uint4*)(p16 + swoff[i]) = o;
        }
    };

    // ---- prologue: 2 chunks in flight, pre-convert chunk 0 ----
    load_stage(0);
    if (total_u > 1) load_stage(1); else cp_commit();
    cp_wait<1>();          // chunk 0 landed (this thread's copies)
    convert(0);

    // ---- per-warp ldmatrix addressing ----
    const int lrow = lane & 15;
    const int lsel = lane >> 4;
    uint32_t swz[4];
    #pragma unroll
    for (int ks = 0; ks < 4; ks++)
        swz[ks] = (uint32_t)(lrow * 128 + (((ks * 2 + lsel) ^ (lrow & 7)) * 16));

    const uint32_t aWarp = sbase + A16_OFF + (uint32_t)(wm * 64) * 128;
    const uint32_t bWarp = sbase + B_OFF + (uint32_t)(wn * 64) * 128;

    const int trow = lane >> 2;
    const int tcol = (lane & 3) * 2;

    float acc[4][8][4];
    #pragma unroll
    for (int i = 0; i < 4; i++)
        #pragma unroll
        for (int j = 0; j < 8; j++)
            #pragma unroll
            for (int k = 0; k < 4; k++) acc[i][j][k] = 0.0f;

    // ---- main loop: one __syncthreads per chunk ----
    for (int u = 0; u < total_u; u++) {
        // Orders prev-iteration smem reads before refills below, and makes
        // chunk u (awaited per-thread last iteration) + A16(u) conversions
        // visible to all warps.
        __syncthreads();

        if (u + 2 < total_u) load_stage(u + 2);   // A32 slot u&1 (dead), B slot (u+2)%3 (dead)
        else                 cp_commit();

        cp_wait<1>();                              // own copies of chunk u+1 landed
        if (u + 1 < total_u) convert(u + 1);       // same-thread A32 read -> A16 (u+1)&1

        const uint32_t aS = aWarp + (u & 1) * A16_TILE;
        const uint32_t bS = bWarp + (u % 3) * B_TILE;

        #pragma unroll
        for (int ks = 0; ks < 4; ks++) {
            uint32_t ahf[4][4], bhf[4][4];
            #pragma unroll
            for (int mf = 0; mf < 4; mf++)
                ldmx4(ahf[mf], aS + mf * 2048 + swz[ks]);
            #pragma unroll
            for (int nf2 = 0; nf2 < 4; nf2++)
                ldmx4(bhf[nf2], bS + nf2 * 2048 + swz[ks]);
            #pragma unroll
            for (int mf = 0; mf < 4; mf++) {
                #pragma unroll
                for (int nf = 0; nf < 8; nf++) {
                    const int nf2 = nf >> 1, sub = nf & 1;
                    mma_fp16(acc[mf][nf], ahf[mf], bhf[nf2][sub], bhf[nf2][sub + 2]);
                }
            }
        }

        // ---- tile finished: epilogue (overlaps in-flight cp.async) ----
        if ((u & 31) == 31) {
            const int t  = bid + (u >> 5) * grid;
            const int bm = (t >> 3) * TILE_M;
            const int bn = (t & 7) * TILE_N;
            const bool isQ = (bn < DK);
            const float* bias = isQ ? bq : bk;
            const int bcol0 = isQ ? bn : (bn - DK);

            #pragma unroll
            for (int mf = 0; mf < 4; mf++) {
                const int r0 = bm + wm * 64 + mf * 16 + trow;
                #pragma unroll
                for (int nf = 0; nf < 8; nf++) {
                    const int coln = wn * 64 + nf * 8 + tcol;
                    const float2 bv = *(const float2*)(bias + bcol0 + coln);
                    __half2 v0 = __floats2half2_rn(acc[mf][nf][0] + bv.x,
                                                   acc[mf][nf][1] + bv.y);
                    __half2 v1 = __floats2half2_rn(acc[mf][nf][2] + bv.x,
                                                   acc[mf][nf][3] + bv.y);
                    *(__half2*)&g_QK[(size_t)r0 * GN + bn + coln]       = v0;
                    *(__half2*)&g_QK[(size_t)(r0 + 8) * GN + bn + coln] = v1;
                    acc[mf][nf][0] = 0.0f; acc[mf][nf][1] = 0.0f;
                    acc[mf][nf][2] = 0.0f; acc[mf][nf][3] = 0.0f;
                }
            }
        }
    }
}

// ---------------------------------------------------------------------------
// Kernel: per-batch attention algebra + output epilogue (R11-proven version)
// ---------------------------------------------------------------------------
__global__ void __launch_bounds__(256) attn_epilogue_kernel(
    const float* __restrict__ img,
    const float* __restrict__ text,
    const float* __restrict__ Wj,
    const float* __restrict__ bj,
    const float* __restrict__ Wbil,
    float* __restrict__ out)
{
    const int b    = blockIdx.x;
    const int tid  = threadIdx.x;
    const int warp = tid >> 5;
    const int lane = tid & 31;

    __shared__ float logits[3][3][3];
    __shared__ float attnI[3][3];
    __shared__ float attnT[3][3];

    for (int idx = warp; idx < 27; idx += 8) {
        const int map = idx / 9;
        const int r   = idx % 9;
        const int q   = r / 3;
        const int s   = r % 3;

        const size_t mi_q = (size_t)(b * 3 + q) * GN;
        const size_t mi_s = (size_t)(b * 3 + s) * GN;
        const size_t mt_q = (size_t)(ROWS + b * 3 + q) * GN;
        const size_t mt_s = (size_t)(ROWS + b * 3 + s) * GN;

        const __half* a;
        const __half* v;
        if (map == 0)      { a = g_QK + mi_q; v = g_QK + mt_s + DK; }
        else if (map == 1) { a = g_QK + mi_q; v = g_QK + mi_s + DK; }
        else               { a = g_QK + mt_q; v = g_QK + mt_s + DK; }

        const uint4* a8 = (const uint4*)a;
        const uint4* v8 = (const uint4*)v;
        float sum = 0.0f;
        #pragma unroll
        for (int t = 0; t < 4; t++) {
            const uint4 av = a8[lane + 32 * t];
            const uint4 vv = v8[lane + 32 * t];
            const __half2* ah = (const __half2*)&av;
            const __half2* vh = (const __half2*)&vv;
            #pragma unroll
            for (int u = 0; u < 4; u++) {
                const float2 af = __half22float2(ah[u]);
                const float2 vf = __half22float2(vh[u]);
                sum += af.x * vf.x + af.y * vf.y;
            }
        }
        #pragma unroll
        for (int off = 16; off > 0; off >>= 1)
            sum += __shfl_xor_sync(0xFFFFFFFFu, sum, off);
        if (lane == 0) logits[map][q][s] = sum;
    }
    __syncthreads();

    if (tid == 0) {
        float p[3][3][3];
        #pragma unroll
        for (int map = 0; map < 3; map++) {
            #pragma unroll
            for (int q = 0; q < 3; q++) {
                float m = logits[map][q][0];
                m = fmaxf(m, logits[map][q][1]);
                m = fmaxf(m, logits[map][q][2]);
                float e0 = __expf(logits[map][q][0] - m);
                float e1 = __expf(logits[map][q][1] - m);
                float e2 = __expf(logits[map][q][2] - m);
                float inv = NORM_FACT / (e0 + e1 + e2);
                p[map][q][0] = e0 * inv;
                p[map][q][1] = e1 * inv;
                p[map][q][2] = e2 * inv;
            }
        }
        float jl[3][3][3];
        #pragma unroll
        for (int map = 0; map < 3; map++)
            #pragma unroll
            for (int q = 0; q < 3; q++)
                #pragma unroll
                for (int o = 0; o < 3; o++)
                    jl[map][q][o] = p[map][q][0] * Wj[o * 3 + 0]
                                  + p[map][q][1] * Wj[o * 3 + 1]
                                  + p[map][q][2] * Wj[o * 3 + 2]
                                  + bj[o];
        #pragma unroll
        for (int q = 0; q < 3; q++) {
            #pragma unroll
            for (int o = 0; o < 3; o++) {
                float accI = 0.0f, accT = 0.0f;
                #pragma unroll
                for (int i = 0; i < 3; i++) {
                    #pragma unroll
                    for (int jx = 0; jx < 3; jx++) {
                        const float w = Wbil[o * 9 + i * 3 + jx];
                        accI += jl[0][q][i] * w * jl[1][q][jx];
                        accT += jl[0][q][i] * w * jl[2][q][jx];
                    }
                }
                attnI[q][o] = accI;
                attnT[q][o] = accT;
            }
        }
    }
    __syncthreads();

    const float4* ib = (const float4*)(img  + (size_t)b * 3 * D);
    const float4* tb = (const float4*)(text + (size_t)b * 3 * D);
    float4* oi = (float4*)(out + (size_t)(b * 3) * D);
    float4* ot = (float4*)(out + (size_t)ROWS * D + (size_t)(b * 3) * D);
    const int D4 = D / 4;

    const float ai00 = attnI[0][0], ai01 = attnI[0][1], ai02 = attnI[0][2];
    const float ai10 = attnI[1][0], ai11 = attnI[1][1], ai12 = attnI[1][2];
    const float ai20 = attnI[2][0], ai21 = attnI[2][1], ai22 = attnI[2][2];
    const float at00 = attnT[0][0], at01 = attnT[0][1], at02 = attnT[0][2];
    const float at10 = attnT[1][0], at11 = attnT[1][1], at12 = attnT[1][2];
    const float at20 = attnT[2][0], at21 = attnT[2][1], at22 = attnT[2][2];

    #pragma unroll
    for (int it = 0; it < 2; it++) {
        const int d = tid + it * 256;
        const float4 i0 = ib[d], i1 = ib[D4 + d], i2 = ib[2 * D4 + d];
        const float4 t0 = tb[d], t1 = tb[D4 + d], t2 = tb[2 * D4 + d];
        float4 r;
        r.x = ai00 * i0.x + ai01 * i1.x + ai02 * i2.x;
        r.y = ai00 * i0.y + ai01 * i1.y + ai02 * i2.y;
        r.z = ai00 * i0.z + ai01 * i1.z + ai02 * i2.z;
        r.w = ai00 * i0.w + ai01 * i1.w + ai02 * i2.w;
        oi[d] = r;
        r.x = ai10 * i0.x + ai11 * i1.x + ai12 * i2.x;
        r.y = ai10 * i0.y + ai11 * i1.y + ai12 * i2.y;
        r.z = ai10 * i0.z + ai11 * i1.z + ai12 * i2.z;
        r.w = ai10 * i0.w + ai11 * i1.w + ai12 * i2.w;
        oi[D4 + d] = r;
        r.x = ai20 * i0.x + ai21 * i1.x + ai22 * i2.x;
        r.y = ai20 * i0.y + ai21 * i1.y + ai22 * i2.y;
        r.z = ai20 * i0.z + ai21 * i1.z + ai22 * i2.z;
        r.w = ai20 * i0.w + ai21 * i1.w + ai22 * i2.w;
        oi[2 * D4 + d] = r;
        r.x = at00 * t0.x + at01 * t1.x + at02 * t2.x;
        r.y = at00 * t0.y + at01 * t1.y + at02 * t2.y;
        r.z = at00 * t0.z + at01 * t1.z + at02 * t2.z;
        r.w = at00 * t0.w + at01 * t1.w + at02 * t2.w;
        ot[d] = r;
        r.x = at10 * t0.x + at11 * t1.x + at12 * t2.x;
        r.y = at10 * t0.y + at11 * t1.y + at12 * t2.y;
        r.z = at10 * t0.z + at11 * t1.z + at12 * t2.z;
        r.w = at10 * t0.w + at11 * t1.w + at12 * t2.w;
        ot[D4 + d] = r;
        r.x = at20 * t0.x + at21 * t1.x + at22 * t2.x;
        r.y = at20 * t0.y + at21 * t1.y + at22 * t2.y;
        r.z = at20 * t0.z + at21 * t1.z + at22 * t2.z;
        r.w = at20 * t0.w + at21 * t1.w + at22 * t2.w;
        ot[2 * D4 + d] = r;
    }
}

// ---------------------------------------------------------------------------
extern "C" void kernel_launch(void* const* d_in, const int* in_sizes, int n_in,
                              void* d_out, int out_size)
{
    const float* img  = (const float*)d_in[0];
    const float* text = (const float*)d_in[1];
    const float* Wq   = (const float*)d_in[2];
    const float* bq   = (const float*)d_in[3];
    const float* Wk   = (const float*)d_in[4];
    const float* bk   = (const float*)d_in[5];
    const float* Wj   = (const float*)d_in[6];
    const float* bj   = (const float*)d_in[7];
    const float* Wbil = (const float*)d_in[8];
    float* out = (float*)d_out;

    static int nsm = 0;
    if (nsm == 0) {
        cudaDeviceGetAttribute(&nsm, cudaDevAttrMultiProcessorCount, 0);
        if (nsm <= 0) nsm = 148;
        cudaFuncSetAttribute(gemm_mma_kernel,
                             cudaFuncAttributeMaxDynamicSharedMemorySize, SMEM_TOTAL);
    }

    // convert B (weights) only — A converted inside the GEMM
    convertB_kernel<<<(unsigned)(B_F8 / 256), 256>>>(Wq, Wk);

    // persistent GEMM with fused A conversion: one CTA per SM
    gemm_mma_kernel<<<nsm, 256, SMEM_TOTAL>>>(img, text, bq, bk);

    attn_epilogue_kernel<<<BATCH, 256>>>(img, text, Wj, bj, Wbil, out);
}

// round 15
// speedup vs baseline: 1.4022x; 1.4022x over previous
#include <cuda_runtime.h>
#include <cuda_fp16.h>
#include <cstdint>

// ---------------------------------------------------------------------------
// Problem constants
// ---------------------------------------------------------------------------
static constexpr int BATCH = 8192;
static constexpr int D     = 2048;           // input feature dim (K of GEMM)
static constexpr int DK    = 1024;           // projection dim
static constexpr int ROWS  = BATCH * 3;      // 24576 rows per tensor
static constexpr int GM    = ROWS * 2;       // 49152 (img rows then text rows)
static constexpr int GN    = 2 * DK;         // 2048  (Q cols then K cols)
static constexpr int GK    = D;              // 2048
static constexpr float NORM_FACT = 0.03125f; // 1/sqrt(1024)

// GEMM tiling (proven config): 128x256 CTA tile, 8 warps (2x4), 64x64 warp
static constexpr int TILE_M = 128;
static constexpr int TILE_N = 256;
static constexpr int BK     = 64;            // fp16 elems per chunk (128B rows)
static constexpr int NCHUNK = GK / BK;       // 32
static constexpr int NSTAGE = 4;

static constexpr int A_TILE = TILE_M * 128;             // 16 KB
static constexpr int B_TILE = TILE_N * 128;             // 32 KB
static constexpr int STAGE_BYTES = A_TILE + B_TILE;     // 48 KB
static constexpr int SMEM_TOTAL  = NSTAGE * STAGE_BYTES; // 192 KB

static constexpr int NTILES_M = GM / TILE_M;  // 384
static constexpr int NTILES_N = GN / TILE_N;  // 8
static constexpr int NTILES   = NTILES_M * NTILES_N;  // 3072

// ---------------------------------------------------------------------------
// Device scratch
// ---------------------------------------------------------------------------
__device__ __align__(16) __half g_A[(size_t)GM * GK];
__device__ __align__(16) __half g_B[(size_t)GN * GK];
__device__ __align__(16) __half g_QK[(size_t)GM * GN];

// ---------------------------------------------------------------------------
// PTX helpers (portable sm_80-era ISA: cp.async, ldmatrix, mma.sync)
// ---------------------------------------------------------------------------
__device__ __forceinline__ uint32_t smem_u32(const void* p) {
    uint32_t a;
    asm("{ .reg .u64 t; cvta.to.shared.u64 t, %1; cvt.u32.u64 %0, t; }" : "=r"(a) : "l"(p));
    return a;
}
__device__ __forceinline__ void cp16(uint32_t dst, const void* src) {
    asm volatile("cp.async.cg.shared.global [%0], [%1], 16;" :: "r"(dst), "l"(src));
}
__device__ __forceinline__ void cp_commit() {
    asm volatile("cp.async.commit_group;" ::: "memory");
}
template <int N>
__device__ __forceinline__ void cp_wait() {
    asm volatile("cp.async.wait_group %0;" :: "n"(N) : "memory");
}
__device__ __forceinline__ void ldmx4(uint32_t* r, uint32_t addr) {
    asm volatile("ldmatrix.sync.aligned.m8n8.x4.shared.b16 {%0,%1,%2,%3}, [%4];"
                 : "=r"(r[0]), "=r"(r[1]), "=r"(r[2]), "=r"(r[3]) : "r"(addr));
}
__device__ __forceinline__ void mma_fp16(float* c, const uint32_t* a, uint32_t b0, uint32_t b1) {
    asm volatile(
        "mma.sync.aligned.m16n8k16.row.col.f32.f16.f16.f32 "
        "{%0,%1,%2,%3}, {%4,%5,%6,%7}, {%8,%9}, {%0,%1,%2,%3};"
        : "+f"(c[0]), "+f"(c[1]), "+f"(c[2]), "+f"(c[3])
        : "r"(a[0]), "r"(a[1]), "r"(a[2]), "r"(a[3]), "r"(b0), "r"(b1));
}
__device__ __forceinline__ uint32_t pack_h2(float x, float y) {
    const __half2 h = __floats2half2_rn(x, y);
    return *(const uint32_t*)&h;
}

// ---------------------------------------------------------------------------
// Fused convert kernel: fp32 -> fp16 for A (img|text) and B (Wq|Wk).
// ---------------------------------------------------------------------------
static constexpr size_t A_F8 = (size_t)GM * GK / 8;
static constexpr size_t B_F8 = (size_t)GN * GK / 8;
static constexpr size_t A_HALF8 = (size_t)ROWS * GK / 8;
static constexpr size_t B_HALF8 = (size_t)DK * GK / 8;

__global__ void convertAB_kernel(const float* __restrict__ img,
                                 const float* __restrict__ text,
                                 const float* __restrict__ Wq,
                                 const float* __restrict__ Wk)
{
    const size_t i = (size_t)blockIdx.x * blockDim.x + threadIdx.x;  // float8 index
    const float4* src;
    uint4* dst;
    size_t off;
    if (i < A_F8) {
        src = (i < A_HALF8) ? (const float4*)img : (const float4*)text;
        off = (i < A_HALF8) ? i : (i - A_HALF8);
        dst = (uint4*)g_A + i;
    } else {
        const size_t j = i - A_F8;
        src = (j < B_HALF8) ? (const float4*)Wq : (const float4*)Wk;
        off = (j < B_HALF8) ? j : (j - B_HALF8);
        dst = (uint4*)g_B + j;
    }
    const float4 v0 = src[2 * off];
    const float4 v1 = src[2 * off + 1];
    uint4 o;
    o.x = pack_h2(v0.x, v0.y);
    o.y = pack_h2(v0.z, v0.w);
    o.z = pack_h2(v1.x, v1.y);
    o.w = pack_h2(v1.z, v1.w);
    *dst = o;
}

// ---------------------------------------------------------------------------
// Persistent mma.sync fp16 GEMM: g_QK = A @ B^T + bias
// grid = #SMs; chunk-continuous 4-stage cp.async ring across tile boundaries.
// 128x256 CTA tile, 8 warps (2x4), 64x64 warp tile, 1 sync per chunk.
// ---------------------------------------------------------------------------
__global__ void __launch_bounds__(256, 1) gemm_mma_kernel(
    const float* __restrict__ bq, const float* __restrict__ bk)
{
    extern __shared__ char smem[];
    const uint32_t sbase = smem_u32(smem);
    const int tid  = threadIdx.x;
    const int warp = tid >> 5;
    const int lane = tid & 31;
    const int bid  = blockIdx.x;
    const int grid = gridDim.x;

    const int wm = warp & 1;     // M half (64 rows)
    const int wn = warp >> 1;    // N quarter (64 cols)

    const int ntiles  = (NTILES - bid + grid - 1) / grid;
    if (ntiles <= 0) return;
    const int total_u = ntiles * NCHUNK;

    // ---- load geometry (tile-independent part) ----
    const int lr  = tid >> 1;          // 0..127
    const int lc0 = (tid & 1) * 4;     // first 16B chunk (0 or 4) of this row
    const size_t rowOffA = (size_t)lr * GK + lc0 * 8;

    uint32_t swoff[4];
    #pragma unroll
    for (int i = 0; i < 4; i++)
        swoff[i] = (uint32_t)(lr * 128 + (((lc0 + i) ^ (lr & 7)) * 16));

    // u -> (tile, chunk); tile -> (bm, bn) with bn fastest (A reuse in L2)
    auto load_stage = [&](int u) {
        const int t  = bid + (u >> 5) * grid;
        const int c  = u & 31;
        const int bm = (t >> 3) * TILE_M;
        const int bn = (t & 7) * TILE_N;
        const __half* gA  = g_A + (size_t)bm * GK + rowOffA + (size_t)c * BK;
        const __half* gB0 = g_B + (size_t)bn * GK + rowOffA + (size_t)c * BK;
        const __half* gB1 = gB0 + (size_t)128 * GK;
        const uint32_t st = sbase + (u % NSTAGE) * STAGE_BYTES;
        #pragma unroll
        for (int i = 0; i < 4; i++) {
            cp16(st +                      swoff[i], gA  + i * 8);
            cp16(st + A_TILE +             swoff[i], gB0 + i * 8);
            cp16(st + A_TILE + 128 * 128 + swoff[i], gB1 + i * 8);
        }
        cp_commit();
    };

    // ---- prologue: 3 stages in flight ----
    load_stage(0);
    if (total_u > 1) load_stage(1); else cp_commit();
    if (total_u > 2) load_stage(2); else cp_commit();

    // ---- per-warp ldmatrix addressing ----
    const int lrow = lane & 15;
    const int lsel = lane >> 4;
    uint32_t swz[4];
    #pragma unroll
    for (int ks = 0; ks < 4; ks++)
        swz[ks] = (uint32_t)(lrow * 128 + (((ks * 2 + lsel) ^ (lrow & 7)) * 16));

    const uint32_t aWarp = sbase + (uint32_t)(wm * 64) * 128;
    const uint32_t bWarp = sbase + A_TILE + (uint32_t)(wn * 64) * 128;

    const int trow = lane >> 2;
    const int tcol = (lane & 3) * 2;

    float acc[4][8][4];
    #pragma unroll
    for (int i = 0; i < 4; i++)
        #pragma unroll
        for (int j = 0; j < 8; j++)
            #pragma unroll
            for (int k = 0; k < 4; k++) acc[i][j][k] = 0.0f;

    // ---- main loop over all chunks of all owned tiles ----
    for (int u = 0; u < total_u; u++) {
        cp_wait<2>();
        __syncthreads();

        if (u + 3 < total_u) load_stage(u + 3);
        else                 cp_commit();

        const uint32_t aS = aWarp + (u % NSTAGE) * STAGE_BYTES;
        const uint32_t bS = bWarp + (u % NSTAGE) * STAGE_BYTES;

        #pragma unroll
        for (int ks = 0; ks < 4; ks++) {
            uint32_t ah[4][4], bh[4][4];
            #pragma unroll
            for (int mf = 0; mf < 4; mf++)
                ldmx4(ah[mf], aS + mf * 2048 + swz[ks]);
            #pragma unroll
            for (int nf2 = 0; nf2 < 4; nf2++)
                ldmx4(bh[nf2], bS + nf2 * 2048 + swz[ks]);
            #pragma unroll
            for (int mf = 0; mf < 4; mf++) {
                #pragma unroll
                for (int nf = 0; nf < 8; nf++) {
                    const int nf2 = nf >> 1, sub = nf & 1;
                    mma_fp16(acc[mf][nf], ah[mf], bh[nf2][sub], bh[nf2][sub + 2]);
                }
            }
        }

        // ---- tile finished: epilogue (overlaps in-flight cp.async) ----
        if ((u & 31) == 31) {
            const int t  = bid + (u >> 5) * grid;
            const int bm = (t >> 3) * TILE_M;
            const int bn = (t & 7) * TILE_N;
            const bool isQ = (bn < DK);
            const float* bias = isQ ? bq : bk;
            const int bcol0 = isQ ? bn : (bn - DK);

            #pragma unroll
            for (int mf = 0; mf < 4; mf++) {
                const int r0 = bm + wm * 64 + mf * 16 + trow;
                #pragma unroll
                for (int nf = 0; nf < 8; nf++) {
                    const int coln = wn * 64 + nf * 8 + tcol;
                    const float2 bv = *(const float2*)(bias + bcol0 + coln);
                    __half2 v0 = __floats2half2_rn(acc[mf][nf][0] + bv.x,
                                                   acc[mf][nf][1] + bv.y);
                    __half2 v1 = __floats2half2_rn(acc[mf][nf][2] + bv.x,
                                                   acc[mf][nf][3] + bv.y);
                    *(__half2*)&g_QK[(size_t)r0 * GN + bn + coln]       = v0;
                    *(__half2*)&g_QK[(size_t)(r0 + 8) * GN + bn + coln] = v1;
                    acc[mf][nf][0] = 0.0f; acc[mf][nf][1] = 0.0f;
                    acc[mf][nf][2] = 0.0f; acc[mf][nf][3] = 0.0f;
                }
            }
        }
    }
}

// ---------------------------------------------------------------------------
// Kernel: per-batch attention algebra + output epilogue (vectorized)
// ---------------------------------------------------------------------------
__global__ void __launch_bounds__(256) attn_epilogue_kernel(
    const float* __restrict__ img,
    const float* __restrict__ text,
    const float* __restrict__ Wj,
    const float* __restrict__ bj,
    const float* __restrict__ Wbil,
    float* __restrict__ out)
{
    const int b    = blockIdx.x;
    const int tid  = threadIdx.x;
    const int warp = tid >> 5;
    const int lane = tid & 31;

    __shared__ float logits[3][3][3];
    __shared__ float attnI[3][3];
    __shared__ float attnT[3][3];

    for (int idx = warp; idx < 27; idx += 8) {
        const int map = idx / 9;
        const int r   = idx % 9;
        const int q   = r / 3;
        const int s   = r % 3;

        const size_t mi_q = (size_t)(b * 3 + q) * GN;
        const size_t mi_s = (size_t)(b * 3 + s) * GN;
        const size_t mt_q = (size_t)(ROWS + b * 3 + q) * GN;
        const size_t mt_s = (size_t)(ROWS + b * 3 + s) * GN;

        const __half* a;
        const __half* v;
        if (map == 0)      { a = g_QK + mi_q; v = g_QK + mt_s + DK; }
        else if (map == 1) { a = g_QK + mi_q; v = g_QK + mi_s + DK; }
        else               { a = g_QK + mt_q; v = g_QK + mt_s + DK; }

        const uint4* a8 = (const uint4*)a;
        const uint4* v8 = (const uint4*)v;
        float sum = 0.0f;
        #pragma unroll
        for (int t = 0; t < 4; t++) {
            const uint4 av = a8[lane + 32 * t];
            const uint4 vv = v8[lane + 32 * t];
            const __half2* ah = (const __half2*)&av;
            const __half2* vh = (const __half2*)&vv;
            #pragma unroll
            for (int u = 0; u < 4; u++) {
                const float2 af = __half22float2(ah[u]);
                const float2 vf = __half22float2(vh[u]);
                sum += af.x * vf.x + af.y * vf.y;
            }
        }
        #pragma unroll
        for (int off = 16; off > 0; off >>= 1)
            sum += __shfl_xor_sync(0xFFFFFFFFu, sum, off);
        if (lane == 0) logits[map][q][s] = sum;
    }
    __syncthreads();

    if (tid == 0) {
        float p[3][3][3];
        #pragma unroll
        for (int map = 0; map < 3; map++) {
            #pragma unroll
            for (int q = 0; q < 3; q++) {
                float m = logits[map][q][0];
                m = fmaxf(m, logits[map][q][1]);
                m = fmaxf(m, logits[map][q][2]);
                float e0 = __expf(logits[map][q][0] - m);
                float e1 = __expf(logits[map][q][1] - m);
                float e2 = __expf(logits[map][q][2] - m);
                float inv = NORM_FACT / (e0 + e1 + e2);
                p[map][q][0] = e0 * inv;
                p[map][q][1] = e1 * inv;
                p[map][q][2] = e2 * inv;
            }
        }
        float jl[3][3][3];
        #pragma unroll
        for (int map = 0; map < 3; map++)
            #pragma unroll
            for (int q = 0; q < 3; q++)
                #pragma unroll
                for (int o = 0; o < 3; o++)
                    jl[map][q][o] = p[map][q][0] * Wj[o * 3 + 0]
                                  + p[map][q][1] * Wj[o * 3 + 1]
                                  + p[map][q][2] * Wj[o * 3 + 2]
                                  + bj[o];
        #pragma unroll
        for (int q = 0; q < 3; q++) {
            #pragma unroll
            for (int o = 0; o < 3; o++) {
                float accI = 0.0f, accT = 0.0f;
                #pragma unroll
                for (int i = 0; i < 3; i++) {
                    #pragma unroll
                    for (int jx = 0; jx < 3; jx++) {
                        const float w = Wbil[o * 9 + i * 3 + jx];
                        accI += jl[0][q][i] * w * jl[1][q][jx];
                        accT += jl[0][q][i] * w * jl[2][q][jx];
                    }
                }
                attnI[q][o] = accI;
                attnT[q][o] = accT;
            }
        }
    }
    __syncthreads();

    const float4* ib = (const float4*)(img  + (size_t)b * 3 * D);
    const float4* tb = (const float4*)(text + (size_t)b * 3 * D);
    float4* oi = (float4*)(out + (size_t)(b * 3) * D);
    float4* ot = (float4*)(out + (size_t)ROWS * D + (size_t)(b * 3) * D);
    const int D4 = D / 4;

    const float ai00 = attnI[0][0], ai01 = attnI[0][1], ai02 = attnI[0][2];
    const float ai10 = attnI[1][0], ai11 = attnI[1][1], ai12 = attnI[1][2];
    const float ai20 = attnI[2][0], ai21 = attnI[2][1], ai22 = attnI[2][2];
    const float at00 = attnT[0][0], at01 = attnT[0][1], at02 = attnT[0][2];
    const float at10 = attnT[1][0], at11 = attnT[1][1], at12 = attnT[1][2];
    const float at20 = attnT[2][0], at21 = attnT[2][1], at22 = attnT[2][2];

    #pragma unroll
    for (int it = 0; it < 2; it++) {
        const int d = tid + it * 256;
        const float4 i0 = ib[d], i1 = ib[D4 + d], i2 = ib[2 * D4 + d];
        const float4 t0 = tb[d], t1 = tb[D4 + d], t2 = tb[2 * D4 + d];
        float4 r;
        r.x = ai00 * i0.x + ai01 * i1.x + ai02 * i2.x;
        r.y = ai00 * i0.y + ai01 * i1.y + ai02 * i2.y;
        r.z = ai00 * i0.z + ai01 * i1.z + ai02 * i2.z;
        r.w = ai00 * i0.w + ai01 * i1.w + ai02 * i2.w;
        oi[d] = r;
        r.x = ai10 * i0.x + ai11 * i1.x + ai12 * i2.x;
        r.y = ai10 * i0.y + ai11 * i1.y + ai12 * i2.y;
        r.z = ai10 * i0.z + ai11 * i1.z + ai12 * i2.z;
        r.w = ai10 * i0.w + ai11 * i1.w + ai12 * i2.w;
        oi[D4 + d] = r;
        r.x = ai20 * i0.x + ai21 * i1.x + ai22 * i2.x;
        r.y = ai20 * i0.y + ai21 * i1.y + ai22 * i2.y;
        r.z = ai20 * i0.z + ai21 * i1.z + ai22 * i2.z;
        r.w = ai20 * i0.w + ai21 * i1.w + ai22 * i2.w;
        oi[2 * D4 + d] = r;
        r.x = at00 * t0.x + at01 * t1.x + at02 * t2.x;
        r.y = at00 * t0.y + at01 * t1.y + at02 * t2.y;
        r.z = at00 * t0.z + at01 * t1.z + at02 * t2.z;
        r.w = at00 * t0.w + at01 * t1.w + at02 * t2.w;
        ot[d] = r;
        r.x = at10 * t0.x + at11 * t1.x + at12 * t2.x;
        r.y = at10 * t0.y + at11 * t1.y + at12 * t2.y;
        r.z = at10 * t0.z + at11 * t1.z + at12 * t2.z;
        r.w = at10 * t0.w + at11 * t1.w + at12 * t2.w;
        ot[D4 + d] = r;
        r.x = at20 * t0.x + at21 * t1.x + at22 * t2.x;
        r.y = at20 * t0.y + at21 * t1.y + at22 * t2.y;
        r.z = at20 * t0.z + at21 * t1.z + at22 * t2.z;
        r.w = at20 * t0.w + at21 * t1.w + at22 * t2.w;
        ot[2 * D4 + d] = r;
    }
}

// ---------------------------------------------------------------------------
extern "C" void kernel_launch(void* const* d_in, const int* in_sizes, int n_in,
                              void* d_out, int out_size)
{
    const float* img  = (const float*)d_in[0];
    const float* text = (const float*)d_in[1];
    const float* Wq   = (const float*)d_in[2];
    const float* bq   = (const float*)d_in[3];
    const float* Wk   = (const float*)d_in[4];
    const float* bk   = (const float*)d_in[5];
    const float* Wj   = (const float*)d_in[6];
    const float* bj   = (const float*)d_in[7];
    const float* Wbil = (const float*)d_in[8];
    float* out = (float*)d_out;

    static int nsm = 0;
    if (nsm == 0) {
        cudaDeviceGetAttribute(&nsm, cudaDevAttrMultiProcessorCount, 0);
        if (nsm <= 0) nsm = 148;
        cudaFuncSetAttribute(gemm_mma_kernel,
                             cudaFuncAttributeMaxDynamicSharedMemorySize, SMEM_TOTAL);
    }

    {   // fused fp32->fp16 conversion for A and B (one launch)
        const size_t total_f8 = A_F8 + B_F8;
        convertAB_kernel<<<(unsigned)(total_f8 / 256), 256>>>(img, text, Wq, Wk);
    }

    // persistent GEMM: one CTA per SM
    gemm_mma_kernel<<<nsm, 256, SMEM_TOTAL>>>(bq, bk);

    attn_epilogue_kernel<<<BATCH, 256>>>(img, text, Wj, bj, Wbil, out);
}